// round 3
// baseline (speedup 1.0000x reference)
#include <cuda_runtime.h>
#include <cuda.h>
#include <cuda_fp16.h>
#include <cstdint>

// ---------------- problem constants ----------------
#define N_NODES 10000
#define IN_DIM  128
#define OUT_DIM 64
#define M_TILE  64
#define K_CHUNK 64
#define NUM_ITERS ((N_NODES + K_CHUNK - 1) / K_CHUNK)   // 157
#define STAGES  3
#define NTHREADS 288

#define RAW_BYTES (M_TILE * K_CHUNK * 4)      // 16384 int32 adj tile
#define A_BYTES   (M_TILE * K_CHUNK * 2)      // 8192 fp16 SW128 A tile
#define B_BYTES   (OUT_DIM * K_CHUNK * 2)     // 8192 fp16 SW128 B tile
#define STAGE_BYTES (RAW_BYTES + A_BYTES + B_BYTES)   // 32768
#define SMEM_MAIN (STAGES * STAGE_BYTES)              // 98304
#define SMEM_TOTAL (SMEM_MAIN + 128 + 1024)

// ---------------- device scratch (no allocs allowed) ----------------
__device__ __align__(1024) __half g_WhT[OUT_DIM * N_NODES];

// ---------------- PTX helpers (plain sm_103-safe: no tcgen05) ----------------
__device__ __forceinline__ uint32_t smem_u32(const void* p) {
    uint32_t a;
    asm("{ .reg .u64 t; cvta.to.shared.u64 t, %1; cvt.u32.u64 %0, t; }" : "=r"(a) : "l"(p));
    return a;
}
#define MBAR_INIT(a,c)  asm volatile("mbarrier.init.shared.b64 [%0], %1;" :: "r"(a), "r"(c) : "memory")
#define MBAR_ARRIVE(a)  asm volatile("mbarrier.arrive.shared.b64 _, [%0];" :: "r"(a) : "memory")
#define MBAR_EXPECT_TX(a,b) asm volatile("mbarrier.arrive.expect_tx.shared.b64 _, [%0], %1;" :: "r"(a), "r"(b) : "memory")

#define MBAR_WAIT(mbar_addr, phase_parity) do {                                \
    uint32_t _mbar = (uint32_t)(mbar_addr);                                    \
    uint32_t _par  = (uint32_t)(phase_parity);                                 \
    uint32_t _done_;                                                           \
    asm volatile("{\n\t.reg .pred p;\n\t"                                      \
        "mbarrier.try_wait.parity.acquire.cta.shared::cta.b64 p, [%1], %2;\n\t"\
        "selp.b32 %0, 1, 0, p;\n\t}"                                           \
        : "=r"(_done_) : "r"(_mbar), "r"(_par) : "memory");                    \
    if (!_done_) {                                                             \
        asm volatile("{\n\t.reg .pred P1;\n\t"                                 \
            "WL_%=:\n\t"                                                       \
            "mbarrier.try_wait.parity.acquire.cta.shared::cta.b64 P1, [%0], %1, 0x989680;\n\t" \
            "@P1 bra.uni WD_%=;\n\t"                                           \
            "bra.uni WL_%=;\n\t"                                               \
            "WD_%=:\n\t}"                                                      \
            :: "r"(_mbar), "r"(_par) : "memory");                              \
    }                                                                          \
} while (0)

#define TMA_LOAD_2D(dst, map, x, y, mbar)                                      \
    asm volatile(                                                              \
        "cp.async.bulk.tensor.2d.shared::cta.global.tile.mbarrier::complete_tx::bytes " \
        "[%0], [%1, {%2, %3}], [%4];"                                          \
        :: "r"((uint32_t)(dst)), "l"(map), "r"((int)(x)), "r"((int)(y)),       \
           "r"((uint32_t)(mbar)) : "memory")

#define LDMATRIX_X4(r0,r1,r2,r3,addr) \
    asm volatile("ldmatrix.sync.aligned.m8n8.x4.shared.b16 {%0,%1,%2,%3}, [%4];" \
        : "=r"(r0),"=r"(r1),"=r"(r2),"=r"(r3) : "r"(addr))

#define HMMA_16816(C, a0,a1,a2,a3, b0,b1) \
    asm volatile("mma.sync.aligned.m16n8k16.row.col.f32.f16.f16.f32 " \
        "{%0,%1,%2,%3}, {%4,%5,%6,%7}, {%8,%9}, {%0,%1,%2,%3};" \
        : "+f"((C)[0]),"+f"((C)[1]),"+f"((C)[2]),"+f"((C)[3]) \
        : "r"(a0),"r"(a1),"r"(a2),"r"(a3),"r"(b0),"r"(b1))

// ---------------- kernel 1: WhT = (h@W)^T in fp16 ----------------
__global__ void prep_kernel(const float* __restrict__ h, const float* __restrict__ W) {
    __shared__ float hs[IN_DIM];
    int i = blockIdx.x;          // node
    int t = threadIdx.x;         // output col (64 threads)
    hs[t]      = h[i * IN_DIM + t];
    hs[t + 64] = h[i * IN_DIM + t + 64];
    __syncthreads();
    float acc = 0.f;
#pragma unroll 8
    for (int k = 0; k < IN_DIM; k++) acc += hs[k] * W[k * OUT_DIM + t];
    g_WhT[t * N_NODES + i] = __float2half(acc);
}

// ---------------- kernel 2: masked mean via HMMA pipeline ----------------
__global__ void __launch_bounds__(NTHREADS, 2) gat_main_kernel(
    const __grid_constant__ CUtensorMap tma_adj,
    const __grid_constant__ CUtensorMap tma_b,
    float* __restrict__ out)
{
    extern __shared__ char smem_raw[];
    const int tid = threadIdx.x;
    const int wid = tid >> 5;
    const int lid = tid & 31;

    uint32_t sb0 = smem_u32(smem_raw);
    uint32_t sbase = (sb0 + 1023u) & ~1023u;
    char* smem = smem_raw + (sbase - sb0);
    const uint32_t mb = sbase + SMEM_MAIN;
    // mbar layout: empty[3] @0, full_raw[3] @24, full_conv[3] @48

    __shared__ int sdeg[M_TILE];

    if (tid == 0) {
        for (int s = 0; s < STAGES; s++) {
            MBAR_INIT(mb + s * 8, 4);          // empty: 4 MMA-warp arrivals
            MBAR_INIT(mb + 24 + s * 8, 1);     // full_raw: TMA tx
            MBAR_INIT(mb + 48 + s * 8, 128);   // full_conv: 128 converter threads
        }
    }
    __syncthreads();

    const int row0 = blockIdx.x * M_TILE;
    float acc[8][4];

    if (tid == 256) {
        // ---------------- TMA producer ----------------
        int s = 0, ph = 1;
        for (int it = 0; it < NUM_ITERS; it++) {
            MBAR_WAIT(mb + s * 8, ph);                       // wait stage empty
            uint32_t dst = sbase + s * STAGE_BYTES;
            uint32_t fr = mb + 24 + s * 8;
            MBAR_EXPECT_TX(fr, RAW_BYTES + B_BYTES);
            TMA_LOAD_2D(dst, &tma_adj, it * K_CHUNK, row0, fr);
            TMA_LOAD_2D(dst + RAW_BYTES + A_BYTES, &tma_b, it * K_CHUNK, 0, fr);
            if (++s == STAGES) { s = 0; ph ^= 1; }
        }
    } else if (wid >= 4 && wid < 8) {
        // ---------------- converters: int32 adj -> fp16 A (SW128) + degree ----------------
        const int ct = tid - 128;                            // 0..127
        int dacc[8] = {0,0,0,0,0,0,0,0};
        int s = 0, ph = 0;
        for (int it = 0; it < NUM_ITERS; it++) {
            MBAR_WAIT(mb + 24 + s * 8, ph);                  // wait TMA data
            const uint4* rawv = (const uint4*)(smem + s * STAGE_BYTES);
            char* aT = smem + s * STAGE_BYTES + RAW_BYTES;
#pragma unroll
            for (int g = 0; g < 8; g++) {
                int idx = g * 128 + ct;                      // linear: conflict-free LDS.128
                uint4 v = rawv[idx];
                dacc[g] += (int)(v.x + v.y + v.z + v.w);
                uint32_t u0 = v.x * 0x3C00u + v.y * 0x3C000000u;  // 2x fp16 1.0/0.0
                uint32_t u1 = v.z * 0x3C00u + v.w * 0x3C000000u;
                uint32_t off = (uint32_t)((idx >> 4) * 128 + (idx & 15) * 8);
                off ^= (off >> 3) & 0x70;                    // SW128 swizzle
                *(uint2*)(aT + off) = make_uint2(u0, u1);
            }
            MBAR_ARRIVE(mb + 48 + s * 8);                    // release A tile
            if (++s == STAGES) { s = 0; ph ^= 1; }
        }
        // degree reduce: row = g*8 + (ct>>4), partials across 16 lanes
#pragma unroll
        for (int g = 0; g < 8; g++) {
            int d = dacc[g];
            d += __shfl_xor_sync(0xffffffffu, d, 1);
            d += __shfl_xor_sync(0xffffffffu, d, 2);
            d += __shfl_xor_sync(0xffffffffu, d, 4);
            d += __shfl_xor_sync(0xffffffffu, d, 8);
            if ((ct & 15) == 0) sdeg[g * 8 + (ct >> 4)] = d;
        }
    } else if (wid < 4) {
        // ---------------- MMA warps: warp w = rows w*16..w*16+15 ----------------
#pragma unroll
        for (int t = 0; t < 8; t++)
#pragma unroll
            for (int p = 0; p < 4; p++) acc[t][p] = 0.f;
        const int sub = lid >> 3, rl = lid & 7;
        int s = 0, ph = 0;
        for (int it = 0; it < NUM_ITERS; it++) {
            MBAR_WAIT(mb + 48 + s * 8, ph);                  // wait converted A (+B)
            uint32_t aBase = sbase + s * STAGE_BYTES + RAW_BYTES;
            uint32_t bBase = aBase + A_BYTES;
#pragma unroll
            for (int kt = 0; kt < 4; kt++) {
                uint32_t a0, a1, a2, a3;
                {
                    int row = wid * 16 + (sub & 1) * 8 + rl;
                    uint32_t off = (uint32_t)(row * 128 + kt * 32 + (sub >> 1) * 16);
                    off ^= (off >> 3) & 0x70;
                    LDMATRIX_X4(a0, a1, a2, a3, aBase + off);
                }
#pragma unroll
                for (int ng = 0; ng < 4; ng++) {
                    uint32_t b0, b1, b2, b3;
                    int nrow = ng * 16 + (sub >> 1) * 8 + rl;
                    uint32_t off = (uint32_t)(nrow * 128 + kt * 32 + (sub & 1) * 16);
                    off ^= (off >> 3) & 0x70;
                    LDMATRIX_X4(b0, b1, b2, b3, bBase + off);
                    HMMA_16816(acc[ng * 2],     a0, a1, a2, a3, b0, b1);
                    HMMA_16816(acc[ng * 2 + 1], a0, a1, a2, a3, b2, b3);
                }
            }
            if (lid == 0) MBAR_ARRIVE(mb + s * 8);           // stage consumed
            if (++s == STAGES) { s = 0; ph ^= 1; }
        }
    }

    __syncthreads();

    // ---------------- epilogue: divide by degree, store ----------------
    if (wid < 4) {
        const int g = lid >> 2, tg = lid & 3;
        const int r0 = wid * 16 + g, r1 = r0 + 8;
        const int i0 = row0 + r0, i1 = row0 + r1;
        float inv0 = 1.0f / (float)sdeg[r0];
        float inv1 = 1.0f / (float)sdeg[r1];
        if (i0 < N_NODES) {
            float* o = out + (size_t)i0 * OUT_DIM + tg * 2;
#pragma unroll
            for (int t = 0; t < 8; t++)
                *(float2*)(o + t * 8) = make_float2(acc[t][0] * inv0, acc[t][1] * inv0);
        }
        if (i1 < N_NODES) {
            float* o = out + (size_t)i1 * OUT_DIM + tg * 2;
#pragma unroll
            for (int t = 0; t < 8; t++)
                *(float2*)(o + t * 8) = make_float2(acc[t][2] * inv1, acc[t][3] * inv1);
        }
    }
}

// ---------------- host ----------------
typedef CUresult (*EncodeFn)(CUtensorMap*, CUtensorMapDataType, cuuint32_t, void*,
                             const cuuint64_t*, const cuuint64_t*, const cuuint32_t*,
                             const cuuint32_t*, CUtensorMapInterleave, CUtensorMapSwizzle,
                             CUtensorMapL2promotion, CUtensorMapFloatOOBfill);

static EncodeFn get_encode_fn() {
    void* fp = nullptr;
    cudaDriverEntryPointQueryResult qr;
#if CUDART_VERSION >= 12050
    cudaGetDriverEntryPointByVersion("cuTensorMapEncodeTiled", &fp, 12000,
                                     cudaEnableDefault, &qr);
#else
    cudaGetDriverEntryPoint("cuTensorMapEncodeTiled", &fp, cudaEnableDefault, &qr);
#endif
    return (EncodeFn)fp;
}

extern "C" void kernel_launch(void* const* d_in, const int* in_sizes, int n_in,
                              void* d_out, int out_size) {
    const float* h   = (const float*)d_in[0];
    void*        adj = (void*)d_in[1];           // int32 [10000,10000]
    const float* W   = (const float*)d_in[2];
    float*       out = (float*)d_out;

    prep_kernel<<<N_NODES, 64>>>(h, W);

    EncodeFn enc = get_encode_fn();
    void* whtPtr = nullptr;
    cudaGetSymbolAddress(&whtPtr, g_WhT);

    CUtensorMap tmaAdj, tmaB;
    {   // adj: int32 [10000][10000], box [64,64], no swizzle
        cuuint64_t dims[2]    = {N_NODES, N_NODES};
        cuuint64_t strides[1] = {(cuuint64_t)N_NODES * 4};
        cuuint32_t box[2]     = {K_CHUNK, M_TILE};
        cuuint32_t es[2]      = {1, 1};
        enc(&tmaAdj, CU_TENSOR_MAP_DATA_TYPE_UINT32, 2, adj, dims, strides, box, es,
            CU_TENSOR_MAP_INTERLEAVE_NONE, CU_TENSOR_MAP_SWIZZLE_NONE,
            CU_TENSOR_MAP_L2_PROMOTION_L2_128B, CU_TENSOR_MAP_FLOAT_OOB_FILL_NONE);
    }
    {   // WhT: fp16 [64][10000], box [64,64], SW128 (row = 128B)
        cuuint64_t dims[2]    = {N_NODES, OUT_DIM};
        cuuint64_t strides[1] = {(cuuint64_t)N_NODES * 2};
        cuuint32_t box[2]     = {K_CHUNK, OUT_DIM};
        cuuint32_t es[2]      = {1, 1};
        enc(&tmaB, CU_TENSOR_MAP_DATA_TYPE_FLOAT16, 2, whtPtr, dims, strides, box, es,
            CU_TENSOR_MAP_INTERLEAVE_NONE, CU_TENSOR_MAP_SWIZZLE_128B,
            CU_TENSOR_MAP_L2_PROMOTION_L2_128B, CU_TENSOR_MAP_FLOAT_OOB_FILL_NONE);
    }

    cudaFuncSetAttribute(gat_main_kernel, cudaFuncAttributeMaxDynamicSharedMemorySize,
                         SMEM_TOTAL);
    int grid = (N_NODES + M_TILE - 1) / M_TILE;   // 157
    gat_main_kernel<<<grid, NTHREADS, SMEM_TOTAL>>>(tmaAdj, tmaB, out);

    (void)in_sizes; (void)n_in; (void)out_size;
}

// round 4
// speedup vs baseline: 1.2561x; 1.2561x over previous
#include <cuda_runtime.h>
#include <cuda.h>
#include <cuda_fp16.h>
#include <cstdint>

// ---------------- problem constants ----------------
#define N_NODES 10000
#define IN_DIM  128
#define OUT_DIM 64
#define M_TILE  80                       // 125 CTAs exactly, 1 per SM, no tail
#define K_CHUNK 64
#define NUM_ITERS ((N_NODES + K_CHUNK - 1) / K_CHUNK)   // 157
#define STAGES  5
#define NTHREADS 320                     // 5 MMA + 4 conv + 1 producer warps

#define RAW_BYTES (M_TILE * K_CHUNK * 4)      // 20480 int32 adj tile
#define A_BYTES   (M_TILE * K_CHUNK * 2)      // 10240 fp16 SW128 A tile
#define B_BYTES   (OUT_DIM * K_CHUNK * 2)     // 8192  fp16 SW128 B tile
#define STAGE_BYTES (RAW_BYTES + A_BYTES + B_BYTES)   // 38912 (38*1024)
#define SMEM_MAIN (STAGES * STAGE_BYTES)              // 194560
#define SMEM_TOTAL (SMEM_MAIN + 128 + 1024)

// ---------------- device scratch (no allocs allowed) ----------------
__device__ __align__(1024) __half g_WhT[OUT_DIM * N_NODES];

// ---------------- PTX helpers (plain sm_103-safe: no tcgen05) ----------------
__device__ __forceinline__ uint32_t smem_u32(const void* p) {
    uint32_t a;
    asm("{ .reg .u64 t; cvta.to.shared.u64 t, %1; cvt.u32.u64 %0, t; }" : "=r"(a) : "l"(p));
    return a;
}
#define MBAR_INIT(a,c)  asm volatile("mbarrier.init.shared.b64 [%0], %1;" :: "r"(a), "r"(c) : "memory")
#define MBAR_ARRIVE(a)  asm volatile("mbarrier.arrive.shared.b64 _, [%0];" :: "r"(a) : "memory")
#define MBAR_EXPECT_TX(a,b) asm volatile("mbarrier.arrive.expect_tx.shared.b64 _, [%0], %1;" :: "r"(a), "r"(b) : "memory")

#define MBAR_WAIT(mbar_addr, phase_parity) do {                                \
    uint32_t _mbar = (uint32_t)(mbar_addr);                                    \
    uint32_t _par  = (uint32_t)(phase_parity);                                 \
    uint32_t _done_;                                                           \
    asm volatile("{\n\t.reg .pred p;\n\t"                                      \
        "mbarrier.try_wait.parity.acquire.cta.shared::cta.b64 p, [%1], %2;\n\t"\
        "selp.b32 %0, 1, 0, p;\n\t}"                                           \
        : "=r"(_done_) : "r"(_mbar), "r"(_par) : "memory");                    \
    if (!_done_) {                                                             \
        asm volatile("{\n\t.reg .pred P1;\n\t"                                 \
            "WL_%=:\n\t"                                                       \
            "mbarrier.try_wait.parity.acquire.cta.shared::cta.b64 P1, [%0], %1, 0x989680;\n\t" \
            "@P1 bra.uni WD_%=;\n\t"                                           \
            "bra.uni WL_%=;\n\t"                                               \
            "WD_%=:\n\t}"                                                      \
            :: "r"(_mbar), "r"(_par) : "memory");                              \
    }                                                                          \
} while (0)

#define TMA_LOAD_2D(dst, map, x, y, mbar)                                      \
    asm volatile(                                                              \
        "cp.async.bulk.tensor.2d.shared::cta.global.tile.mbarrier::complete_tx::bytes " \
        "[%0], [%1, {%2, %3}], [%4];"                                          \
        :: "r"((uint32_t)(dst)), "l"(map), "r"((int)(x)), "r"((int)(y)),       \
           "r"((uint32_t)(mbar)) : "memory")

#define LDMATRIX_X4(r0,r1,r2,r3,addr) \
    asm volatile("ldmatrix.sync.aligned.m8n8.x4.shared.b16 {%0,%1,%2,%3}, [%4];" \
        : "=r"(r0),"=r"(r1),"=r"(r2),"=r"(r3) : "r"(addr))

#define HMMA_16816(C, a0,a1,a2,a3, b0,b1) \
    asm volatile("mma.sync.aligned.m16n8k16.row.col.f32.f16.f16.f32 " \
        "{%0,%1,%2,%3}, {%4,%5,%6,%7}, {%8,%9}, {%0,%1,%2,%3};" \
        : "+f"((C)[0]),"+f"((C)[1]),"+f"((C)[2]),"+f"((C)[3]) \
        : "r"(a0),"r"(a1),"r"(a2),"r"(a3),"r"(b0),"r"(b1))

// ---------------- kernel 1: WhT = (h@W)^T in fp16 (16 nodes / block) ----------------
#define PREP_NODES 16
__global__ void __launch_bounds__(256) prep_kernel(
    const float* __restrict__ h, const float* __restrict__ W)
{
    __shared__ float Ws[IN_DIM * OUT_DIM];      // 32KB
    __shared__ float hsm[PREP_NODES * IN_DIM];  // 8KB
    const int tid = threadIdx.x;
    const int node0 = blockIdx.x * PREP_NODES;

    // stage W (8192 floats) and h rows (2048 floats) via float4
    const float4* W4 = (const float4*)W;
    float4* Ws4 = (float4*)Ws;
#pragma unroll
    for (int i = 0; i < 8; i++) Ws4[tid + i * 256] = W4[tid + i * 256];
    const float4* h4 = (const float4*)(h + (size_t)node0 * IN_DIM);
    float4* hs4 = (float4*)hsm;
#pragma unroll
    for (int i = 0; i < 2; i++) hs4[tid + i * 256] = h4[tid + i * 256];
    __syncthreads();

    const int col = tid & 63;
    const int nb = (tid >> 6) * 4;              // 4 nodes per thread
    float acc[4] = {0.f, 0.f, 0.f, 0.f};
#pragma unroll 4
    for (int k = 0; k < IN_DIM; k++) {
        float w = Ws[k * OUT_DIM + col];
#pragma unroll
        for (int n = 0; n < 4; n++) acc[n] += hsm[(nb + n) * IN_DIM + k] * w;
    }
#pragma unroll
    for (int n = 0; n < 4; n++)
        g_WhT[col * N_NODES + node0 + nb + n] = __float2half(acc[n]);
}

// ---------------- kernel 2: masked mean via HMMA pipeline ----------------
__global__ void __launch_bounds__(NTHREADS, 1) gat_main_kernel(
    const __grid_constant__ CUtensorMap tma_adj,
    const __grid_constant__ CUtensorMap tma_b,
    float* __restrict__ out)
{
    extern __shared__ char smem_raw[];
    const int tid = threadIdx.x;
    const int wid = tid >> 5;
    const int lid = tid & 31;

    uint32_t sb0 = smem_u32(smem_raw);
    uint32_t sbase = (sb0 + 1023u) & ~1023u;
    char* smem = smem_raw + (sbase - sb0);
    const uint32_t mb = sbase + SMEM_MAIN;
    // mbar layout: empty[5] @0, full_raw[5] @40, full_conv[5] @80

    __shared__ int sdeg[M_TILE];

    if (tid == 0) {
        for (int s = 0; s < STAGES; s++) {
            MBAR_INIT(mb + s * 8, 5);           // empty: 5 MMA-warp arrivals
            MBAR_INIT(mb + 40 + s * 8, 1);      // full_raw: TMA tx
            MBAR_INIT(mb + 80 + s * 8, 128);    // full_conv: 128 conv threads
        }
    }
    __syncthreads();

    const int row0 = blockIdx.x * M_TILE;
    float acc[8][4];

    if (tid == 288) {
        // ---------------- TMA producer ----------------
        int s = 0, ph = 1;
        for (int it = 0; it < NUM_ITERS; it++) {
            MBAR_WAIT(mb + s * 8, ph);                       // wait stage empty
            uint32_t dst = sbase + s * STAGE_BYTES;
            uint32_t fr = mb + 40 + s * 8;
            MBAR_EXPECT_TX(fr, RAW_BYTES + B_BYTES);
            TMA_LOAD_2D(dst, &tma_adj, it * K_CHUNK, row0, fr);
            TMA_LOAD_2D(dst + RAW_BYTES + A_BYTES, &tma_b, it * K_CHUNK, 0, fr);
            if (++s == STAGES) { s = 0; ph ^= 1; }
        }
    } else if (wid >= 5 && wid < 9) {
        // ---------------- converters: int32 adj -> fp16 A (SW128) + degree ----------------
        const int ct = tid - 160;                            // 0..127
        int dacc[10];
#pragma unroll
        for (int g = 0; g < 10; g++) dacc[g] = 0;
        int s = 0, ph = 0;
        for (int it = 0; it < NUM_ITERS; it++) {
            MBAR_WAIT(mb + 40 + s * 8, ph);                  // wait TMA data
            const uint4* rawv = (const uint4*)(smem + s * STAGE_BYTES);
            char* aT = smem + s * STAGE_BYTES + RAW_BYTES;
#pragma unroll
            for (int g = 0; g < 10; g++) {
                int idx = g * 128 + ct;                      // linear: conflict-free LDS.128
                uint4 v = rawv[idx];
                dacc[g] += (int)(v.x + v.y + v.z + v.w);
                uint32_t u0 = v.x * 0x3C00u + v.y * 0x3C000000u;  // 2x fp16 {1.0,0.0}
                uint32_t u1 = v.z * 0x3C00u + v.w * 0x3C000000u;
                uint32_t off = (uint32_t)((idx >> 4) * 128 + (idx & 15) * 8);
                off ^= (off >> 3) & 0x70;                    // SW128 swizzle
                *(uint2*)(aT + off) = make_uint2(u0, u1);
            }
            MBAR_ARRIVE(mb + 80 + s * 8);                    // release A tile
            if (++s == STAGES) { s = 0; ph ^= 1; }
        }
        // degree reduce: row = g*8 + (ct>>4); partials across the 16 lanes of a half-warp
#pragma unroll
        for (int g = 0; g < 10; g++) {
            int d = dacc[g];
            d += __shfl_xor_sync(0xffffffffu, d, 1);
            d += __shfl_xor_sync(0xffffffffu, d, 2);
            d += __shfl_xor_sync(0xffffffffu, d, 4);
            d += __shfl_xor_sync(0xffffffffu, d, 8);
            if ((ct & 15) == 0) sdeg[g * 8 + (ct >> 4)] = d;
        }
    } else if (wid < 5) {
        // ---------------- MMA warps: warp w = rows w*16..w*16+15 ----------------
#pragma unroll
        for (int t = 0; t < 8; t++)
#pragma unroll
            for (int p = 0; p < 4; p++) acc[t][p] = 0.f;
        const int sub = lid >> 3, rl = lid & 7;
        int s = 0, ph = 0;
        for (int it = 0; it < NUM_ITERS; it++) {
            MBAR_WAIT(mb + 80 + s * 8, ph);                  // wait converted A (+B)
            uint32_t aBase = sbase + s * STAGE_BYTES + RAW_BYTES;
            uint32_t bBase = aBase + A_BYTES;
#pragma unroll
            for (int kt = 0; kt < 4; kt++) {
                uint32_t a0, a1, a2, a3;
                {
                    int row = wid * 16 + (sub & 1) * 8 + rl;
                    uint32_t off = (uint32_t)(row * 128 + kt * 32 + (sub >> 1) * 16);
                    off ^= (off >> 3) & 0x70;
                    LDMATRIX_X4(a0, a1, a2, a3, aBase + off);
                }
#pragma unroll
                for (int ng = 0; ng < 4; ng++) {
                    uint32_t b0, b1, b2, b3;
                    int nrow = ng * 16 + (sub >> 1) * 8 + rl;
                    uint32_t off = (uint32_t)(nrow * 128 + kt * 32 + (sub & 1) * 16);
                    off ^= (off >> 3) & 0x70;
                    LDMATRIX_X4(b0, b1, b2, b3, bBase + off);
                    HMMA_16816(acc[ng * 2],     a0, a1, a2, a3, b0, b1);
                    HMMA_16816(acc[ng * 2 + 1], a0, a1, a2, a3, b2, b3);
                }
            }
            if (lid == 0) MBAR_ARRIVE(mb + s * 8);           // stage consumed
            if (++s == STAGES) { s = 0; ph ^= 1; }
        }
    }

    __syncthreads();

    // ---------------- epilogue: divide by degree, store ----------------
    if (wid < 5) {
        const int g = lid >> 2, tg = lid & 3;
        const int r0 = wid * 16 + g, r1 = r0 + 8;
        const int i0 = row0 + r0, i1 = row0 + r1;
        float inv0 = 1.0f / (float)sdeg[r0];
        float inv1 = 1.0f / (float)sdeg[r1];
        {
            float* o = out + (size_t)i0 * OUT_DIM + tg * 2;
#pragma unroll
            for (int t = 0; t < 8; t++)
                *(float2*)(o + t * 8) = make_float2(acc[t][0] * inv0, acc[t][1] * inv0);
        }
        {
            float* o = out + (size_t)i1 * OUT_DIM + tg * 2;
#pragma unroll
            for (int t = 0; t < 8; t++)
                *(float2*)(o + t * 8) = make_float2(acc[t][2] * inv1, acc[t][3] * inv1);
        }
    }
}

// ---------------- host ----------------
typedef CUresult (*EncodeFn)(CUtensorMap*, CUtensorMapDataType, cuuint32_t, void*,
                             const cuuint64_t*, const cuuint64_t*, const cuuint32_t*,
                             const cuuint32_t*, CUtensorMapInterleave, CUtensorMapSwizzle,
                             CUtensorMapL2promotion, CUtensorMapFloatOOBfill);

static EncodeFn get_encode_fn() {
    void* fp = nullptr;
    cudaDriverEntryPointQueryResult qr;
#if CUDART_VERSION >= 12050
    cudaGetDriverEntryPointByVersion("cuTensorMapEncodeTiled", &fp, 12000,
                                     cudaEnableDefault, &qr);
#else
    cudaGetDriverEntryPoint("cuTensorMapEncodeTiled", &fp, cudaEnableDefault, &qr);
#endif
    return (EncodeFn)fp;
}

extern "C" void kernel_launch(void* const* d_in, const int* in_sizes, int n_in,
                              void* d_out, int out_size) {
    const float* h   = (const float*)d_in[0];
    void*        adj = (void*)d_in[1];           // int32 [10000,10000]
    const float* W   = (const float*)d_in[2];
    float*       out = (float*)d_out;

    prep_kernel<<<N_NODES / PREP_NODES, 256>>>(h, W);

    EncodeFn enc = get_encode_fn();
    void* whtPtr = nullptr;
    cudaGetSymbolAddress(&whtPtr, g_WhT);

    CUtensorMap tmaAdj, tmaB;
    {   // adj: int32 [10000][10000], box [64,80], no swizzle
        cuuint64_t dims[2]    = {N_NODES, N_NODES};
        cuuint64_t strides[1] = {(cuuint64_t)N_NODES * 4};
        cuuint32_t box[2]     = {K_CHUNK, M_TILE};
        cuuint32_t es[2]      = {1, 1};
        enc(&tmaAdj, CU_TENSOR_MAP_DATA_TYPE_UINT32, 2, adj, dims, strides, box, es,
            CU_TENSOR_MAP_INTERLEAVE_NONE, CU_TENSOR_MAP_SWIZZLE_NONE,
            CU_TENSOR_MAP_L2_PROMOTION_L2_128B, CU_TENSOR_MAP_FLOAT_OOB_FILL_NONE);
    }
    {   // WhT: fp16 [64][10000], box [64,64], SW128 (row = 128B)
        cuuint64_t dims[2]    = {N_NODES, OUT_DIM};
        cuuint64_t strides[1] = {(cuuint64_t)N_NODES * 2};
        cuuint32_t box[2]     = {K_CHUNK, OUT_DIM};
        cuuint32_t es[2]      = {1, 1};
        enc(&tmaB, CU_TENSOR_MAP_DATA_TYPE_FLOAT16, 2, whtPtr, dims, strides, box, es,
            CU_TENSOR_MAP_INTERLEAVE_NONE, CU_TENSOR_MAP_SWIZZLE_128B,
            CU_TENSOR_MAP_L2_PROMOTION_L2_128B, CU_TENSOR_MAP_FLOAT_OOB_FILL_NONE);
    }

    cudaFuncSetAttribute(gat_main_kernel, cudaFuncAttributeMaxDynamicSharedMemorySize,
                         SMEM_TOTAL);
    int grid = N_NODES / M_TILE;   // 125 == one CTA per SM, single balanced wave
    gat_main_kernel<<<grid, NTHREADS, SMEM_TOTAL>>>(tmaAdj, tmaB, out);

    (void)in_sizes; (void)n_in; (void)out_size;
}